// round 17
// baseline (speedup 1.0000x reference)
#include <cuda_runtime.h>

#define NN 65536
#define EE 1048576
#define HH 64
#define GG 256
#define CC 10
#define BN_EPS 1e-5f

// Scratch (device globals: allocation-free rule). float4 => guaranteed 16B alignment.
__device__ float4 d_h1[NN * 16];
__device__ float4 d_h2[NN * 16];
__device__ float4 d_pool4[GG * 16];       // per-graph feature sums (256 x 64)
__device__ float  d_cnt[GG];              // per-graph counts (pooling)
__device__ float  d_dis[NN];              // rsqrt(1 + in-degree)
__device__ float  d_par[5 * 192];         // canonical: conv_b, gamma, beta, mean, var
// CSR (grouped by dst, built once)
__device__ int    d_hist[NN];
__device__ int    d_scan[NN];
__device__ int    d_rowptr[NN];
__device__ int    d_cursor[NN];
__device__ int    d_bsum[256];
__device__ int    d_bsum2[256];
__device__ int    d_eidx[EE];

#define P_CONVB (d_par + 0 * 192)
#define P_GAMMA (d_par + 1 * 192)
#define P_BETA  (d_par + 2 * 192)
#define P_MEAN  (d_par + 3 * 192)
#define P_VAR   (d_par + 4 * 192)

// ------------------------------------------------- classify the five 192-elem params
__global__ void k_classify(const float* __restrict__ a0, const float* __restrict__ a1,
                           const float* __restrict__ a2, const float* __restrict__ a3,
                           const float* __restrict__ a4) {
    const float* as[5] = {a0, a1, a2, a3, a4};
    int t = threadIdx.x;            // 192 threads
    float v[5];
    bool zero_all[5], one_all[5], big_all[5];
#pragma unroll
    for (int k = 0; k < 5; k++) {
        v[k] = as[k][t];
        zero_all[k] = __syncthreads_and(v[k] == 0.0f);
        one_all[k]  = __syncthreads_and(v[k] == 1.0f);
        big_all[k]  = __syncthreads_and(v[k] > 0.5f);
    }
    int beta = -1, gamma = -1, var = -1;
#pragma unroll
    for (int k = 0; k < 5; k++) {
        if (zero_all[k]) beta = k;
        else if (one_all[k]) gamma = k;
        else if (big_all[k]) var = k;
    }
    int rem[2]; int n = 0;
#pragma unroll
    for (int k = 0; k < 5; k++)
        if (k != beta && k != gamma && k != var && n < 2) rem[n++] = k;
    int convb, mean;
    if (gamma < beta) { convb = rem[0]; mean = rem[1]; }   // dict/signature order: conv_b first
    else              { convb = rem[1]; mean = rem[0]; }   // alpha order: bn_mean first
    P_CONVB[t] = v[convb];
    P_GAMMA[t] = v[gamma];
    P_BETA[t]  = v[beta];
    P_MEAN[t]  = v[mean];
    P_VAR[t]   = v[var];
}

// ---------------------------------------------------------------- CSR build
__global__ void k_zero_hist() {
    int i = blockIdx.x * 256 + threadIdx.x;
    if (i < NN) d_hist[i] = 0;
}

__global__ void k_hist(const int* __restrict__ dst) {
    int e = blockIdx.x * 256 + threadIdx.x;
    if (e < EE) atomicAdd(&d_hist[__ldg(dst + e) & (NN - 1)], 1);
}

__global__ void k_scan_block() {           // 256 blocks x 256 threads
    __shared__ int sh[256];
    int tid = threadIdx.x;
    int gid = blockIdx.x * 256 + tid;
    int v = d_hist[gid];
    sh[tid] = v;
    __syncthreads();
    for (int off = 1; off < 256; off <<= 1) {
        int t = (tid >= off) ? sh[tid - off] : 0;
        __syncthreads();
        sh[tid] += t;
        __syncthreads();
    }
    d_scan[gid] = sh[tid] - v;             // exclusive within block
    if (tid == 255) d_bsum[blockIdx.x] = sh[tid];
}

__global__ void k_scan_top() {             // 1 block x 256 threads
    __shared__ int sh[256];
    int tid = threadIdx.x;
    int v = d_bsum[tid];
    sh[tid] = v;
    __syncthreads();
    for (int off = 1; off < 256; off <<= 1) {
        int t = (tid >= off) ? sh[tid - off] : 0;
        __syncthreads();
        sh[tid] += t;
        __syncthreads();
    }
    d_bsum2[tid] = sh[tid] - v;            // exclusive
}

__global__ void k_scan_add() {             // 256 blocks x 256 threads
    int gid = blockIdx.x * 256 + threadIdx.x;
    int rp = d_scan[gid] + d_bsum2[blockIdx.x];
    d_rowptr[gid] = rp;
    d_cursor[gid] = rp;
    d_dis[gid] = rsqrtf(1.0f + (float)d_hist[gid]);
}

__global__ void k_fill(const int* __restrict__ src, const int* __restrict__ dst) {
    int e = blockIdx.x * 256 + threadIdx.x;
    if (e < EE) {
        int sv = __ldg(src + e) & (NN - 1);
        int dv = __ldg(dst + e) & (NN - 1);
        int p = atomicAdd(&d_cursor[dv], 1);
        d_eidx[p] = sv;
    }
}

// ---------------------------------------------------------------- fused layer
// By linearity: q[row] = h[row]*dis[row] + sum_src h[src]*dis[src]
//               out    = relu(bn(dis[row]*(q @ W) + b)) (+ res)
// 1 warp per row; lane = eo*16+q for gather; lane owns 2 output cols for the GEMM.
// Layer 2 feeds the pool directly (no h write).
__global__ __launch_bounds__(256) void k_fused(const float* __restrict__ x,
                                               const float* __restrict__ conv_w,
                                               const int* __restrict__ batch,
                                               int layer) {
    __shared__ __align__(16) float Ws[HH * HH];
    const float* W = conv_w + layer * HH * HH;
    int tid = threadIdx.x;           // 256
#pragma unroll
    for (int i = 0; i < 4; i++)
        reinterpret_cast<float4*>(Ws)[tid + i * 256] =
            reinterpret_cast<const float4*>(W)[tid + i * 256];
    __syncthreads();

    int warp = tid >> 5;
    int lane = tid & 31;
    int eo = lane >> 4;
    int q = lane & 15;
    int row = blockIdx.x * 8 + warp;   // grid = NN/8

    const float4* hin;
    const float* resf = nullptr;
    if (layer == 0)      { hin = reinterpret_cast<const float4*>(x); }
    else if (layer == 1) { hin = d_h1; resf = reinterpret_cast<const float*>(d_h1); }
    else                 { hin = d_h2; resf = reinterpret_cast<const float*>(d_h2); }

    int start = d_rowptr[row];
    int cnt = d_hist[row];
    float disr = d_dis[row];

    // gather: p = h*dis ; self-loop seeds stream 0
    float4 acc;
    if (eo == 0) {
        float4 v = __ldg(hin + (size_t)row * 16 + q);
        acc = make_float4(v.x * disr, v.y * disr, v.z * disr, v.w * disr);
    } else {
        acc = make_float4(0.f, 0.f, 0.f, 0.f);
    }
    for (int t = eo; t < cnt; t += 2) {
        int s = __ldg(d_eidx + start + t);
        float ds = __ldg(d_dis + s);
        float4 v = __ldg(hin + (size_t)s * 16 + q);
        acc.x = fmaf(v.x, ds, acc.x);
        acc.y = fmaf(v.y, ds, acc.y);
        acc.z = fmaf(v.z, ds, acc.z);
        acc.w = fmaf(v.w, ds, acc.w);
    }
    // fold the two streams: all 32 lanes now hold the sum for quad (lane&15)
    acc.x += __shfl_xor_sync(0xffffffffu, acc.x, 16);
    acc.y += __shfl_xor_sync(0xffffffffu, acc.y, 16);
    acc.z += __shfl_xor_sync(0xffffffffu, acc.z, 16);
    acc.w += __shfl_xor_sync(0xffffffffu, acc.w, 16);

    // per-row GEMM: out[j] = sum_k q[k]*W[k][j]; lane owns cols j0, j0+1
    int j0 = lane * 2;
    float o0 = 0.f, o1 = 0.f;
#pragma unroll
    for (int kq = 0; kq < 16; kq++) {
        float qx = __shfl_sync(0xffffffffu, acc.x, kq);
        float qy = __shfl_sync(0xffffffffu, acc.y, kq);
        float qz = __shfl_sync(0xffffffffu, acc.z, kq);
        float qw = __shfl_sync(0xffffffffu, acc.w, kq);
        const float* wb = Ws + (kq * 4) * HH + j0;
        float2 w0 = *reinterpret_cast<const float2*>(wb);
        float2 w1 = *reinterpret_cast<const float2*>(wb + HH);
        float2 w2 = *reinterpret_cast<const float2*>(wb + 2 * HH);
        float2 w3 = *reinterpret_cast<const float2*>(wb + 3 * HH);
        o0 = fmaf(qx, w0.x, o0); o1 = fmaf(qx, w0.y, o1);
        o0 = fmaf(qy, w1.x, o0); o1 = fmaf(qy, w1.y, o1);
        o0 = fmaf(qz, w2.x, o0); o1 = fmaf(qz, w2.y, o1);
        o0 = fmaf(qw, w3.x, o0); o1 = fmaf(qw, w3.y, o1);
    }

    // BN + ReLU (+ residual) epilogue
    int jp = layer * HH + j0;
    float sc0 = P_GAMMA[jp]     * rsqrtf(P_VAR[jp]     + BN_EPS);
    float sc1 = P_GAMMA[jp + 1] * rsqrtf(P_VAR[jp + 1] + BN_EPS);
    float v0 = sc0 * (disr * o0 + P_CONVB[jp]     - P_MEAN[jp])     + P_BETA[jp];
    float v1 = sc1 * (disr * o1 + P_CONVB[jp + 1] - P_MEAN[jp + 1]) + P_BETA[jp + 1];
    v0 = fmaxf(v0, 0.0f);
    v1 = fmaxf(v1, 0.0f);
    if (resf) {
        float2 r = *reinterpret_cast<const float2*>(resf + (size_t)row * HH + j0);
        v0 += r.x;
        v1 += r.y;
    }

    if (layer < 2) {
        float* op = reinterpret_cast<float*>((layer == 1) ? d_h2 : d_h1);
        *reinterpret_cast<float2*>(op + (size_t)row * HH + j0) = make_float2(v0, v1);
    } else {
        // feed pooling directly
        int b = __ldg(batch + row) & (GG - 1);
        float* pp = reinterpret_cast<float*>(d_pool4) + b * HH + j0;
        asm volatile("red.global.add.v2.f32 [%0], {%1,%2};"
                     :: "l"(pp), "f"(v0), "f"(v1) : "memory");
        if (lane == 0) {
            float* cp = d_cnt + b;
            asm volatile("red.global.add.f32 [%0], %1;" :: "l"(cp), "f"(1.0f) : "memory");
        }
    }
}

// ---------------------------------------------------------------- pooling buffers
__global__ void k_pool_zero() {
    int i = blockIdx.x * blockDim.x + threadIdx.x;
    if (i < GG * 16) d_pool4[i] = make_float4(0.0f, 0.0f, 0.0f, 0.0f);
    if (i < GG) d_cnt[i] = 0.0f;
}

// ---------------------------------------------------------------- classifier (1 block/graph)
__global__ __launch_bounds__(64) void k_classifier(const float* __restrict__ w1,
                                                   const float* __restrict__ b1,
                                                   const float* __restrict__ w2,
                                                   const float* __restrict__ b2,
                                                   float* __restrict__ out) {
    int g = blockIdx.x;        // 256 blocks
    int j = threadIdx.x;       // 64 threads
    __shared__ float mean_s[HH];
    __shared__ float z[HH];
    __shared__ float logits[CC];

    float c = d_cnt[g];
    mean_s[j] = reinterpret_cast<const float*>(d_pool4)[g * HH + j] / fmaxf(c, 1.0f);
    __syncthreads();

    float a = __ldg(b1 + j);
#pragma unroll 8
    for (int k = 0; k < HH; k++) a = fmaf(mean_s[k], __ldg(w1 + k * HH + j), a);
    z[j] = fmaxf(a, 0.0f);
    __syncthreads();

    if (j < CC) {
        float acc = __ldg(b2 + j);
#pragma unroll 8
        for (int k = 0; k < HH; k++) acc = fmaf(z[k], __ldg(w2 + k * CC + j), acc);
        logits[j] = acc;
    }
    __syncthreads();

    if (j == 0) {
        float m = -1e30f;
        for (int cc = 0; cc < CC; cc++) m = fmaxf(m, logits[cc]);
        float se = 0.0f;
        for (int cc = 0; cc < CC; cc++) se += expf(logits[cc] - m);
        float lse = m + logf(se);
        for (int cc = 0; cc < CC; cc++) out[g * CC + cc] = logits[cc] - lse;
    }
}

// ---------------------------------------------------------------- launch
extern "C" void kernel_launch(void* const* d_in, const int* in_sizes, int n_in,
                              void* d_out, int out_size) {
    // Resolve inputs by element count (robust to metadata ordering).
    const float *x = nullptr, *conv_w = nullptr;
    const float *cls_w1 = nullptr, *cls_b1 = nullptr, *cls_w2 = nullptr, *cls_b2 = nullptr;
    const int *ei = nullptr, *batch = nullptr;
    const float* p192[5] = {nullptr, nullptr, nullptr, nullptr, nullptr};
    int n192 = 0;
    for (int i = 0; i < n_in; i++) {
        switch (in_sizes[i]) {
            case NN * HH:      x      = (const float*)d_in[i]; break;   // 4194304
            case 2 * EE:       ei     = (const int*)d_in[i];   break;   // 2097152
            case NN:           batch  = (const int*)d_in[i];   break;   // 65536
            case 3 * HH * HH:  conv_w = (const float*)d_in[i]; break;   // 12288
            case HH * HH:      cls_w1 = (const float*)d_in[i]; break;   // 4096
            case HH * CC:      cls_w2 = (const float*)d_in[i]; break;   // 640
            case HH:           cls_b1 = (const float*)d_in[i]; break;   // 64
            case CC:           cls_b2 = (const float*)d_in[i]; break;   // 10
            case 3 * HH:       if (n192 < 5) p192[n192++] = (const float*)d_in[i]; break;
            default: break;
        }
    }
    const int* src = ei;
    const int* dst = ei + EE;
    float* out = (float*)d_out;

    k_classify<<<1, 192>>>(p192[0], p192[1], p192[2], p192[3], p192[4]);

    // CSR build (grouped by dst) + dis
    k_zero_hist<<<NN / 256, 256>>>();
    k_hist<<<EE / 256, 256>>>(dst);
    k_scan_block<<<256, 256>>>();
    k_scan_top<<<1, 256>>>();
    k_scan_add<<<256, 256>>>();
    k_fill<<<EE / 256, 256>>>(src, dst);
    k_pool_zero<<<(GG * 16 + 255) / 256, 256>>>();

    for (int l = 0; l < 3; l++)
        k_fused<<<NN / 8, 256>>>(x, conv_w, batch, l);

    k_classifier<<<GG, 64>>>(cls_w1, cls_b1, cls_w2, cls_b2, out);
}